// round 1
// baseline (speedup 1.0000x reference)
#include <cuda_runtime.h>
#include <cstdint>

// Problem dims
#define BB 64
#define TT 512
#define DD 512
#define NTOK (BB * TT)                 // 32768
#define GBLK 128                        // persistent blocks (<= SM count, 1 wave)

static const size_t BTD = (size_t)NTOK * DD;   // 16,777,216

// ----------------------------------------------------------------------------
// Scratch (device globals — no allocations allowed)
// ----------------------------------------------------------------------------
__device__ float g_Xi[16777216];
__device__ float g_Xc[16777216];
__device__ float g_Xo[16777216];
__device__ float g_h[BB * DD];
__device__ unsigned g_bar;

// ----------------------------------------------------------------------------
// Helpers
// ----------------------------------------------------------------------------
__device__ __forceinline__ float tf32r(float x) {
    uint32_t u;
    asm("cvt.rna.tf32.f32 %0, %1;" : "=r"(u) : "f"(x));
    return __uint_as_float(u);
}

__device__ __forceinline__ void mma8(float (&d)[4], const uint32_t a[4], const uint32_t b[2]) {
    asm volatile(
        "mma.sync.aligned.m16n8k8.row.col.f32.tf32.tf32.f32 "
        "{%0,%1,%2,%3}, {%4,%5,%6,%7}, {%8,%9}, {%0,%1,%2,%3};\n"
        : "+f"(d[0]), "+f"(d[1]), "+f"(d[2]), "+f"(d[3])
        : "r"(a[0]), "r"(a[1]), "r"(a[2]), "r"(a[3]), "r"(b[0]), "r"(b[1]));
}

__device__ __forceinline__ float sigf(float x) {
    return 1.0f / (1.0f + __expf(-x));
}

__device__ __forceinline__ void grid_sync(unsigned target) {
    __syncthreads();
    if (threadIdx.x == 0) {
        __threadfence();                 // release (cumulative: covers block's STGs)
        atomicAdd(&g_bar, 1u);
        while (*(volatile unsigned*)&g_bar < target) { }
        __threadfence();                 // acquire
    }
    __syncthreads();
}

__global__ void init_kernel() { g_bar = 0u; }

// ----------------------------------------------------------------------------
// Kernel 1: input projection  Y[m,n] = sum_k X[m,k] * W[n,k] + bias[n]
// BM=128, BN=64, BK=32, 256 threads, warp grid 4(m) x 2(n), per-warp 32x32
// ----------------------------------------------------------------------------
__global__ __launch_bounds__(256) void proj_kernel(
    const float* __restrict__ X,
    const float* __restrict__ W,
    const float* __restrict__ bias,
    int which)
{
    __shared__ float A_s[128 * 36];
    __shared__ float B_s[64 * 36];

    float* __restrict__ Y = (which == 0) ? g_Xi : (which == 1) ? g_Xc : g_Xo;

    const int tid  = threadIdx.x;
    const int lane = tid & 31;
    const int wid  = tid >> 5;
    const int gid  = lane >> 2;   // 0..7
    const int t4   = lane & 3;    // 0..3
    const int wm   = wid & 3;     // 0..3  (M)
    const int wn   = wid >> 2;    // 0..1  (N)
    const int bm   = blockIdx.x;  // 0..255
    const int bn   = blockIdx.y;  // 0..7

    const float* Xp = X + (size_t)bm * 128 * 512;
    const float* Wp = W + (size_t)bn * 64 * 512;

    float acc[2][4][4] = {};

    for (int kc = 0; kc < 16; ++kc) {
        __syncthreads();
        // Stage A tile (128 x 32)
        #pragma unroll
        for (int p = 0; p < 4; ++p) {
            int r  = (tid >> 3) + p * 32;
            int c4 = (tid & 7) << 2;
            float4 v = *(const float4*)(Xp + (size_t)r * 512 + kc * 32 + c4);
            v.x = tf32r(v.x); v.y = tf32r(v.y); v.z = tf32r(v.z); v.w = tf32r(v.w);
            *(float4*)&A_s[r * 36 + c4] = v;
        }
        // Stage B tile (64 x 32)
        #pragma unroll
        for (int p = 0; p < 2; ++p) {
            int r  = (tid >> 3) + p * 32;
            int c4 = (tid & 7) << 2;
            float4 v = *(const float4*)(Wp + (size_t)r * 512 + kc * 32 + c4);
            v.x = tf32r(v.x); v.y = tf32r(v.y); v.z = tf32r(v.z); v.w = tf32r(v.w);
            *(float4*)&B_s[r * 36 + c4] = v;
        }
        __syncthreads();

        #pragma unroll
        for (int k8 = 0; k8 < 4; ++k8) {
            uint32_t aF[2][4], bF[4][2];
            const int ka = k8 * 8 + t4;
            #pragma unroll
            for (int mt2 = 0; mt2 < 2; ++mt2) {
                int ar = (wm * 32 + mt2 * 16 + gid) * 36 + ka;
                aF[mt2][0] = __float_as_uint(A_s[ar]);
                aF[mt2][1] = __float_as_uint(A_s[ar + 8 * 36]);
                aF[mt2][2] = __float_as_uint(A_s[ar + 4]);
                aF[mt2][3] = __float_as_uint(A_s[ar + 8 * 36 + 4]);
            }
            #pragma unroll
            for (int nt2 = 0; nt2 < 4; ++nt2) {
                int br = (wn * 32 + nt2 * 8 + gid) * 36 + ka;
                bF[nt2][0] = __float_as_uint(B_s[br]);
                bF[nt2][1] = __float_as_uint(B_s[br + 4]);
            }
            #pragma unroll
            for (int mt2 = 0; mt2 < 2; ++mt2)
                #pragma unroll
                for (int nt2 = 0; nt2 < 4; ++nt2)
                    mma8(acc[mt2][nt2], aF[mt2], bF[nt2]);
        }
    }

    // Epilogue: add bias, store
    #pragma unroll
    for (int mt2 = 0; mt2 < 2; ++mt2) {
        #pragma unroll
        for (int nt2 = 0; nt2 < 4; ++nt2) {
            int m = bm * 128 + wm * 32 + mt2 * 16 + gid;
            int n = bn * 64 + wn * 32 + nt2 * 8 + 2 * t4;
            float b0 = bias[n], b1 = bias[n + 1];
            Y[(size_t)m * 512 + n]           = acc[mt2][nt2][0] + b0;
            Y[(size_t)m * 512 + n + 1]       = acc[mt2][nt2][1] + b1;
            Y[(size_t)(m + 8) * 512 + n]     = acc[mt2][nt2][2] + b0;
            Y[(size_t)(m + 8) * 512 + n + 1] = acc[mt2][nt2][3] + b1;
        }
    }
}

// ----------------------------------------------------------------------------
// Kernel 2: persistent recurrence.
// 128 blocks x 256 threads. Block owns h-cols [4*bx, 4*bx+4) for all 4 gates.
// Per step: Z[64 x 16] = h[64 x 512] @ Ublk[16 x 512]^T via tf32 mma, then gates.
// U slice cached in SMEM for the whole kernel.
// ----------------------------------------------------------------------------
__global__ __launch_bounds__(256) void lstm_rec_kernel(
    const float* __restrict__ Ui, const float* __restrict__ Uf,
    const float* __restrict__ Uc, const float* __restrict__ Uo,
    const float* __restrict__ bUf, const float* __restrict__ bUc,
    const float* __restrict__ bUo, float* __restrict__ out)
{
    __shared__ float U_s[16 * 516];   // 33 KB: 16 gate-cols x K=512 (pad 516)
    __shared__ float h_s[64 * 36];    // 9 KB: h chunk 64 x 32 (pad 36)
    __shared__ float Z_s[64 * 16];    // 4 KB
    __shared__ float c_s[256];        // 1 KB

    const int tid  = threadIdx.x;
    const int lane = tid & 31;
    const int wid  = tid >> 5;
    const int gid  = lane >> 2;
    const int t4   = lane & 3;
    const int mt   = wid & 3;    // m tile (batch 16-row group)
    const int nt   = wid >> 2;   // n tile (gate-col 8-group)
    const int n0   = blockIdx.x * 4;
    const int eb   = tid >> 2;   // 0..63 batch for elementwise
    const int ec   = tid & 3;    // 0..3 local h-col

    // Load U slice: rows 0-3 = Ui cols n0..n0+3, 4-7 = Uf, 8-11 = Uc, 12-15 = Uo
    for (int idx = tid; idx < 16 * 512; idx += 256) {
        int r = idx >> 9;
        int k = idx & 511;
        int g = r >> 2;
        int n = n0 + (r & 3);
        const float* Up = (g == 0) ? Ui : (g == 1) ? Uf : (g == 2) ? Uc : Uo;
        U_s[r * 516 + k] = tf32r(Up[(size_t)n * 512 + k]);
    }
    c_s[tid] = 0.0f;
    g_h[eb * 512 + n0 + ec] = 0.0f;

    const float bUf_r = bUf[n0 + ec];
    const float bUc_r = bUc[n0 + ec];
    const float bUo_r = bUo[n0 + ec];

    unsigned bar_t = GBLK;
    grid_sync(bar_t);   // all g_h slices zeroed & visible

    const size_t btd = (size_t)NTOK * DD;

    for (int t = 0; t < TT; ++t) {
        // Prefetch this thread's x terms (independent of h)
        const size_t xidx = ((size_t)eb * TT + t) * DD + n0 + ec;
        const float xiv = g_Xi[xidx];
        const float xcv = g_Xc[xidx];
        const float xov = g_Xo[xidx];

        float acc0[4] = {}, acc1[4] = {};

        for (int kc = 0; kc < 16; ++kc) {
            __syncthreads();
            // Stage h chunk (64 x 32), L1-bypassing (g_h rewritten every step)
            #pragma unroll
            for (int p = 0; p < 2; ++p) {
                int idx = tid + p * 256;
                int row = idx >> 3;
                int c4  = (idx & 7) << 2;
                float4 v = __ldcg((const float4*)(g_h + row * 512 + kc * 32 + c4));
                *(float4*)&h_s[row * 36 + c4] = v;
            }
            __syncthreads();

            const int arow = (mt * 16 + gid) * 36;
            const int brow = (nt * 8 + gid) * 516 + kc * 32;
            #pragma unroll
            for (int k8 = 0; k8 < 4; ++k8) {
                uint32_t a[4], b[2];
                const int ka = k8 * 8 + t4;
                a[0] = __float_as_uint(h_s[arow + ka]);
                a[1] = __float_as_uint(h_s[arow + 8 * 36 + ka]);
                a[2] = __float_as_uint(h_s[arow + ka + 4]);
                a[3] = __float_as_uint(h_s[arow + 8 * 36 + ka + 4]);
                b[0] = __float_as_uint(U_s[brow + ka]);
                b[1] = __float_as_uint(U_s[brow + ka + 4]);
                if (k8 & 1) mma8(acc1, a, b);
                else        mma8(acc0, a, b);
            }
        }

        const float d0 = acc0[0] + acc1[0];
        const float d1 = acc0[1] + acc1[1];
        const float d2 = acc0[2] + acc1[2];
        const float d3 = acc0[3] + acc1[3];

        const int zr = mt * 16 + gid;
        const int zc = nt * 8 + 2 * t4;
        Z_s[zr * 16 + zc]           = d0;
        Z_s[zr * 16 + zc + 1]       = d1;
        Z_s[(zr + 8) * 16 + zc]     = d2;
        Z_s[(zr + 8) * 16 + zc + 1] = d3;
        __syncthreads();

        // Elementwise gates: one (batch, col) per thread
        const float zi  = Z_s[eb * 16 + ec];
        const float zf  = Z_s[eb * 16 + 4 + ec];
        const float zcv = Z_s[eb * 16 + 8 + ec];
        const float zo  = Z_s[eb * 16 + 12 + ec];

        const float ig = sigf(xiv + zi);
        const float fg = sigf(xiv + zf + bUf_r);      // reference quirk: uses xi
        const float cn = fg * c_s[tid] + ig * tanhf(xcv + zcv + bUc_r);
        const float og = sigf(xov + zo + bUo_r);
        const float hn = og * tanhf(cn);

        c_s[tid] = cn;
        out[xidx]       = hn;   // H
        out[btd + xidx] = cn;   // C
        g_h[eb * 512 + n0 + ec] = tf32r(hn);

        bar_t += GBLK;
        grid_sync(bar_t);
    }
}

// ----------------------------------------------------------------------------
// Launch
// ----------------------------------------------------------------------------
extern "C" void kernel_launch(void* const* d_in, const int* in_sizes, int n_in,
                              void* d_out, int out_size) {
    (void)in_sizes; (void)n_in; (void)out_size;

    const float* X   = (const float*)d_in[0];
    const float* Wi  = (const float*)d_in[1];
    const float* bi  = (const float*)d_in[2];
    // d_in[3]=Wf, d_in[4]=bf: unused (reference computes Xf but never uses it)
    const float* Wc  = (const float*)d_in[5];
    const float* bc  = (const float*)d_in[6];
    const float* Wo  = (const float*)d_in[7];
    const float* bo  = (const float*)d_in[8];
    const float* Ui  = (const float*)d_in[9];
    const float* Uf  = (const float*)d_in[10];
    const float* bUf = (const float*)d_in[11];
    const float* Uc  = (const float*)d_in[12];
    const float* bUc = (const float*)d_in[13];
    const float* Uo  = (const float*)d_in[14];
    const float* bUo = (const float*)d_in[15];
    float* out = (float*)d_out;

    init_kernel<<<1, 1>>>();

    dim3 pgrid(NTOK / 128, 8);
    proj_kernel<<<pgrid, 256>>>(X, Wi, bi, 0);
    proj_kernel<<<pgrid, 256>>>(X, Wc, bc, 1);
    proj_kernel<<<pgrid, 256>>>(X, Wo, bo, 2);

    lstm_rec_kernel<<<GBLK, 256>>>(Ui, Uf, Uc, Uo, bUf, bUc, bUo, out);
}

// round 2
// speedup vs baseline: 1.7626x; 1.7626x over previous
#include <cuda_runtime.h>
#include <cstdint>

// Problem dims
#define BB 64
#define TT 512
#define DD 512
#define NTOK (BB * TT)                 // 32768
#define GBLK 128                       // persistent blocks (<= SM count, 1 wave)

#define USTR 516                        // SMEM row strides (== 4 mod 32 -> conflict-free LDS.128)
#define HSTR 516

// ----------------------------------------------------------------------------
// Scratch (device globals — no allocations allowed)
// ----------------------------------------------------------------------------
__device__ float g_Xi[16777216];
__device__ float g_Xc[16777216];
__device__ float g_Xo[16777216];
__device__ float g_h[BB * DD];          // stored COLUMN-PERMUTED per 32-col chunk
__device__ unsigned g_bar;

// ----------------------------------------------------------------------------
// Helpers
// ----------------------------------------------------------------------------
__device__ __forceinline__ float tf32r(float x) {
    uint32_t u;
    asm("cvt.rna.tf32.f32 %0, %1;" : "=r"(u) : "f"(x));
    return __uint_as_float(u);
}
#define f2u __float_as_uint

__device__ __forceinline__ void mma8(float (&d)[4], const uint32_t a[4], const uint32_t b[2]) {
    asm volatile(
        "mma.sync.aligned.m16n8k8.row.col.f32.tf32.tf32.f32 "
        "{%0,%1,%2,%3}, {%4,%5,%6,%7}, {%8,%9}, {%0,%1,%2,%3};\n"
        : "+f"(d[0]), "+f"(d[1]), "+f"(d[2]), "+f"(d[3])
        : "r"(a[0]), "r"(a[1]), "r"(a[2]), "r"(a[3]), "r"(b[0]), "r"(b[1]));
}

__device__ __forceinline__ float sigf(float x) {
    return 1.0f / (1.0f + __expf(-x));
}

__device__ __forceinline__ void cp16(uint32_t dst, const void* src) {
    asm volatile("cp.async.cg.shared.global [%0], [%1], 16;" :: "r"(dst), "l"(src) : "memory");
}

__device__ __forceinline__ void grid_sync(unsigned target) {
    __syncthreads();
    if (threadIdx.x == 0) {
        __threadfence();                 // release
        atomicAdd(&g_bar, 1u);
        while (*(volatile unsigned*)&g_bar < target) { }
        __threadfence();                 // acquire
    }
    __syncthreads();
}

__global__ void init_kernel() { g_bar = 0u; }

// ----------------------------------------------------------------------------
// Kernel 1: input projection  Y[m,n] = sum_k X[m,k] * W[n,k] + bias[n]
// (unchanged from R1 — proven correct; 171us each)
// ----------------------------------------------------------------------------
__global__ __launch_bounds__(256) void proj_kernel(
    const float* __restrict__ X,
    const float* __restrict__ W,
    const float* __restrict__ bias,
    int which)
{
    __shared__ float A_s[128 * 36];
    __shared__ float B_s[64 * 36];

    float* __restrict__ Y = (which == 0) ? g_Xi : (which == 1) ? g_Xc : g_Xo;

    const int tid  = threadIdx.x;
    const int lane = tid & 31;
    const int wid  = tid >> 5;
    const int gid  = lane >> 2;
    const int t4   = lane & 3;
    const int wm   = wid & 3;
    const int wn   = wid >> 2;
    const int bm   = blockIdx.x;
    const int bn   = blockIdx.y;

    const float* Xp = X + (size_t)bm * 128 * 512;
    const float* Wp = W + (size_t)bn * 64 * 512;

    float acc[2][4][4] = {};

    for (int kc = 0; kc < 16; ++kc) {
        __syncthreads();
        #pragma unroll
        for (int p = 0; p < 4; ++p) {
            int r  = (tid >> 3) + p * 32;
            int c4 = (tid & 7) << 2;
            float4 v = *(const float4*)(Xp + (size_t)r * 512 + kc * 32 + c4);
            v.x = tf32r(v.x); v.y = tf32r(v.y); v.z = tf32r(v.z); v.w = tf32r(v.w);
            *(float4*)&A_s[r * 36 + c4] = v;
        }
        #pragma unroll
        for (int p = 0; p < 2; ++p) {
            int r  = (tid >> 3) + p * 32;
            int c4 = (tid & 7) << 2;
            float4 v = *(const float4*)(Wp + (size_t)r * 512 + kc * 32 + c4);
            v.x = tf32r(v.x); v.y = tf32r(v.y); v.z = tf32r(v.z); v.w = tf32r(v.w);
            *(float4*)&B_s[r * 36 + c4] = v;
        }
        __syncthreads();

        #pragma unroll
        for (int k8 = 0; k8 < 4; ++k8) {
            uint32_t aF[2][4], bF[4][2];
            const int ka = k8 * 8 + t4;
            #pragma unroll
            for (int mt2 = 0; mt2 < 2; ++mt2) {
                int ar = (wm * 32 + mt2 * 16 + gid) * 36 + ka;
                aF[mt2][0] = f2u(A_s[ar]);
                aF[mt2][1] = f2u(A_s[ar + 8 * 36]);
                aF[mt2][2] = f2u(A_s[ar + 4]);
                aF[mt2][3] = f2u(A_s[ar + 8 * 36 + 4]);
            }
            #pragma unroll
            for (int nt2 = 0; nt2 < 4; ++nt2) {
                int br = (wn * 32 + nt2 * 8 + gid) * 36 + ka;
                bF[nt2][0] = f2u(B_s[br]);
                bF[nt2][1] = f2u(B_s[br + 4]);
            }
            #pragma unroll
            for (int mt2 = 0; mt2 < 2; ++mt2)
                #pragma unroll
                for (int nt2 = 0; nt2 < 4; ++nt2)
                    mma8(acc[mt2][nt2], aF[mt2], bF[nt2]);
        }
    }

    #pragma unroll
    for (int mt2 = 0; mt2 < 2; ++mt2) {
        #pragma unroll
        for (int nt2 = 0; nt2 < 4; ++nt2) {
            int m = bm * 128 + wm * 32 + mt2 * 16 + gid;
            int n = bn * 64 + wn * 32 + nt2 * 8 + 2 * t4;
            float b0 = bias[n], b1 = bias[n + 1];
            Y[(size_t)m * 512 + n]           = acc[mt2][nt2][0] + b0;
            Y[(size_t)m * 512 + n + 1]       = acc[mt2][nt2][1] + b1;
            Y[(size_t)(m + 8) * 512 + n]     = acc[mt2][nt2][2] + b0;
            Y[(size_t)(m + 8) * 512 + n + 1] = acc[mt2][nt2][3] + b1;
        }
    }
}

// ----------------------------------------------------------------------------
// Kernel 2: persistent recurrence. 128 blocks x 256 threads.
// Full h (64x512) staged to SMEM each step via pipelined cp.async.cg.
// h stored in global COLUMN-PERMUTED: within each 32-col chunk, logical col c
// lives at physical (c&3)*8 + (c>>2), so a thread's 8 MMA k-values are a
// contiguous pair of float4s.
// ----------------------------------------------------------------------------
__global__ __launch_bounds__(256, 1) void lstm_rec_kernel(
    const float* __restrict__ Ui, const float* __restrict__ Uf,
    const float* __restrict__ Uc, const float* __restrict__ Uo,
    const float* __restrict__ bUf, const float* __restrict__ bUc,
    const float* __restrict__ bUo, float* __restrict__ out)
{
    extern __shared__ float dyn[];
    float* U_s = dyn;                    // 16 x USTR  (33 KB)
    float* h_s = dyn + 16 * USTR;        // 64 x HSTR  (132 KB)
    __shared__ float Z_s[64 * 16];
    __shared__ float c_s[256];

    const int tid  = threadIdx.x;
    const int lane = tid & 31;
    const int wid  = tid >> 5;
    const int gid  = lane >> 2;
    const int t4   = lane & 3;
    const int mt   = wid & 3;    // m tile
    const int nt   = wid >> 2;   // n tile
    const int bx   = blockIdx.x;
    const int n0   = bx * 4;
    const int eb   = tid >> 2;   // batch row for elementwise
    const int ec   = tid & 3;    // local gate-col

    // Load U slice, permuted per 32-col chunk. rows: 0-3 Ui, 4-7 Uf, 8-11 Uc, 12-15 Uo
    for (int idx = tid; idx < 16 * 512; idx += 256) {
        int r = idx >> 9;
        int k = idx & 511;
        int g = r >> 2;
        int n = n0 + (r & 3);
        const float* Up = (g == 0) ? Ui : (g == 1) ? Uf : (g == 2) ? Uc : Uo;
        int pk = (k & ~31) + (k & 3) * 8 + ((k >> 2) & 7);
        U_s[r * USTR + pk] = tf32r(Up[(size_t)n * 512 + k]);
    }
    c_s[tid] = 0.0f;

    // This thread's permuted h column
    const int pcol = ((bx >> 3) << 5) + (ec << 3) + (bx & 7);
    g_h[eb * 512 + pcol] = 0.0f;

    const float bUf_r = bUf[n0 + ec];
    const float bUc_r = bUc[n0 + ec];
    const float bUo_r = bUo[n0 + ec];

    unsigned bar_t = GBLK;
    grid_sync(bar_t);   // all g_h zeros visible

    const size_t btd = (size_t)NTOK * DD;
    size_t xidx = (size_t)eb * TT * DD + n0 + ec;   // t = 0
    float xiv = __ldcs(&g_Xi[xidx]);
    float xcv = __ldcs(&g_Xc[xidx]);
    float xov = __ldcs(&g_Xo[xidx]);

    const uint32_t hbase = (uint32_t)__cvta_generic_to_shared(h_s);
    const int r0 = tid >> 3;        // 0..31
    const int c0 = tid & 7;         // 0..7 (float4 index within chunk)

    const float* Arow0 = h_s + (mt * 16 + gid) * HSTR + t4 * 8;
    const float* Arow1 = Arow0 + 8 * HSTR;
    const float* Brow  = U_s + (nt * 8 + gid) * USTR + t4 * 8;

    for (int t = 0; t < TT; ++t) {
        // Issue all 16 h-chunk loads (each chunk = 64 rows x 8 float4s), one group per chunk
        #pragma unroll
        for (int kc = 0; kc < 16; ++kc) {
            cp16(hbase + (uint32_t)(r0 * HSTR + kc * 32 + c0 * 4) * 4,
                 g_h + r0 * 512 + kc * 32 + c0 * 4);
            cp16(hbase + (uint32_t)((r0 + 32) * HSTR + kc * 32 + c0 * 4) * 4,
                 g_h + (r0 + 32) * 512 + kc * 32 + c0 * 4);
            asm volatile("cp.async.commit_group;" ::: "memory");
        }

        // Prefetch next-step x while MMAs run
        float xiv_n = 0.f, xcv_n = 0.f, xov_n = 0.f;
        if (t + 1 < TT) {
            xiv_n = __ldcs(&g_Xi[xidx + DD]);
            xcv_n = __ldcs(&g_Xc[xidx + DD]);
            xov_n = __ldcs(&g_Xo[xidx + DD]);
        }

        float acc0[4] = {}, acc1[4] = {};

        #define COMPUTE_KC(kc) { \
            const float4 alo0 = *(const float4*)(Arow0 + (kc) * 32); \
            const float4 alo1 = *(const float4*)(Arow0 + (kc) * 32 + 4); \
            const float4 ahi0 = *(const float4*)(Arow1 + (kc) * 32); \
            const float4 ahi1 = *(const float4*)(Arow1 + (kc) * 32 + 4); \
            const float4 bv0  = *(const float4*)(Brow  + (kc) * 32); \
            const float4 bv1  = *(const float4*)(Brow  + (kc) * 32 + 4); \
            uint32_t a[4], b[2]; \
            a[0]=f2u(alo0.x); a[1]=f2u(ahi0.x); a[2]=f2u(alo0.y); a[3]=f2u(ahi0.y); \
            b[0]=f2u(bv0.x);  b[1]=f2u(bv0.y);  mma8(acc0, a, b); \
            a[0]=f2u(alo0.z); a[1]=f2u(ahi0.z); a[2]=f2u(alo0.w); a[3]=f2u(ahi0.w); \
            b[0]=f2u(bv0.z);  b[1]=f2u(bv0.w);  mma8(acc1, a, b); \
            a[0]=f2u(alo1.x); a[1]=f2u(ahi1.x); a[2]=f2u(alo1.y); a[3]=f2u(ahi1.y); \
            b[0]=f2u(bv1.x);  b[1]=f2u(bv1.y);  mma8(acc0, a, b); \
            a[0]=f2u(alo1.z); a[1]=f2u(ahi1.z); a[2]=f2u(alo1.w); a[3]=f2u(ahi1.w); \
            b[0]=f2u(bv1.z);  b[1]=f2u(bv1.w);  mma8(acc1, a, b); \
        }

        asm volatile("cp.async.wait_group 12;" ::: "memory");
        __syncthreads();
        COMPUTE_KC(0)  COMPUTE_KC(1)  COMPUTE_KC(2)  COMPUTE_KC(3)
        asm volatile("cp.async.wait_group 8;" ::: "memory");
        __syncthreads();
        COMPUTE_KC(4)  COMPUTE_KC(5)  COMPUTE_KC(6)  COMPUTE_KC(7)
        asm volatile("cp.async.wait_group 4;" ::: "memory");
        __syncthreads();
        COMPUTE_KC(8)  COMPUTE_KC(9)  COMPUTE_KC(10) COMPUTE_KC(11)
        asm volatile("cp.async.wait_group 0;" ::: "memory");
        __syncthreads();
        COMPUTE_KC(12) COMPUTE_KC(13) COMPUTE_KC(14) COMPUTE_KC(15)

        #undef COMPUTE_KC

        const int zr = mt * 16 + gid;
        const int zc = nt * 8 + 2 * t4;
        Z_s[zr * 16 + zc]           = acc0[0] + acc1[0];
        Z_s[zr * 16 + zc + 1]       = acc0[1] + acc1[1];
        Z_s[(zr + 8) * 16 + zc]     = acc0[2] + acc1[2];
        Z_s[(zr + 8) * 16 + zc + 1] = acc0[3] + acc1[3];
        __syncthreads();

        // Elementwise gates: one (batch, col) per thread
        const float zi  = Z_s[eb * 16 + ec];
        const float zf  = Z_s[eb * 16 + 4 + ec];
        const float zcv = Z_s[eb * 16 + 8 + ec];
        const float zo  = Z_s[eb * 16 + 12 + ec];

        const float ig = sigf(xiv + zi);
        const float fg = sigf(xiv + zf + bUf_r);          // reference quirk: uses xi
        const float cn = fg * c_s[tid] + ig * tanhf(xcv + zcv + bUc_r);
        const float og = sigf(xov + zo + bUo_r);
        const float hn = og * tanhf(cn);

        c_s[tid] = cn;
        g_h[eb * 512 + pcol] = tf32r(hn);     // permuted store (critical path)
        out[xidx]       = hn;                  // H
        out[btd + xidx] = cn;                  // C

        xiv = xiv_n; xcv = xcv_n; xov = xov_n;
        xidx += DD;

        bar_t += GBLK;
        if (t + 1 < TT) grid_sync(bar_t);      // skip final barrier
    }
}

// ----------------------------------------------------------------------------
// Launch
// ----------------------------------------------------------------------------
extern "C" void kernel_launch(void* const* d_in, const int* in_sizes, int n_in,
                              void* d_out, int out_size) {
    (void)in_sizes; (void)n_in; (void)out_size;

    const float* X   = (const float*)d_in[0];
    const float* Wi  = (const float*)d_in[1];
    const float* bi  = (const float*)d_in[2];
    // d_in[3]=Wf, d_in[4]=bf unused (reference computes Xf but never uses it)
    const float* Wc  = (const float*)d_in[5];
    const float* bc  = (const float*)d_in[6];
    const float* Wo  = (const float*)d_in[7];
    const float* bo  = (const float*)d_in[8];
    const float* Ui  = (const float*)d_in[9];
    const float* Uf  = (const float*)d_in[10];
    const float* bUf = (const float*)d_in[11];
    const float* Uc  = (const float*)d_in[12];
    const float* bUc = (const float*)d_in[13];
    const float* Uo  = (const float*)d_in[14];
    const float* bUo = (const float*)d_in[15];
    float* out = (float*)d_out;

    static const int dyn_smem = (16 + 64) * USTR * 4;   // 165,120 B
    cudaFuncSetAttribute(lstm_rec_kernel,
                         cudaFuncAttributeMaxDynamicSharedMemorySize, dyn_smem);

    init_kernel<<<1, 1>>>();

    dim3 pgrid(NTOK / 128, 8);
    proj_kernel<<<pgrid, 256>>>(X, Wi, bi, 0);
    proj_kernel<<<pgrid, 256>>>(X, Wc, bc, 1);
    proj_kernel<<<pgrid, 256>>>(X, Wo, bo, 2);

    lstm_rec_kernel<<<GBLK, 256, dyn_smem>>>(Ui, Uf, Uc, Uo, bUf, bUc, bUo, out);
}

// round 3
// speedup vs baseline: 2.2341x; 1.2675x over previous
#include <cuda_runtime.h>
#include <cstdint>

// Problem dims
#define BB 64
#define TT 512
#define DD 512
#define NTOK (BB * TT)                 // 32768

// Recurrence decomposition: 4 independent batch-groups x 32 blocks
#define NGRP  4
#define GBLKS 32                        // blocks per group
#define NB    16                        // batches per group
#define NC    16                        // logical h-cols per block (x4 gates = 64)

#define USTR 516                        // SMEM row strides (== 4 mod 32 -> conflict-free LDS.128)
#define HSTR 516

// ----------------------------------------------------------------------------
// Scratch (device globals — no allocations allowed)
// ----------------------------------------------------------------------------
__device__ float g_Xi[16777216];
__device__ float g_Xc[16777216];
__device__ float g_Xo[16777216];
__device__ float g_h[BB * DD];          // COLUMN-PERMUTED per 32-col chunk
__device__ unsigned g_bars[NGRP * 32];  // one counter per group, 128B apart

// ----------------------------------------------------------------------------
// Helpers
// ----------------------------------------------------------------------------
__device__ __forceinline__ float tf32r(float x) {
    uint32_t u;
    asm("cvt.rna.tf32.f32 %0, %1;" : "=r"(u) : "f"(x));
    return __uint_as_float(u);
}
#define f2u __float_as_uint

__device__ __forceinline__ void mma8(float (&d)[4], const uint32_t a[4], const uint32_t b[2]) {
    asm volatile(
        "mma.sync.aligned.m16n8k8.row.col.f32.tf32.tf32.f32 "
        "{%0,%1,%2,%3}, {%4,%5,%6,%7}, {%8,%9}, {%0,%1,%2,%3};\n"
        : "+f"(d[0]), "+f"(d[1]), "+f"(d[2]), "+f"(d[3])
        : "r"(a[0]), "r"(a[1]), "r"(a[2]), "r"(a[3]), "r"(b[0]), "r"(b[1]));
}

__device__ __forceinline__ float sigf(float x) {
    return 1.0f / (1.0f + __expf(-x));
}

__device__ __forceinline__ void cp16(uint32_t dst, const void* src) {
    asm volatile("cp.async.cg.shared.global [%0], [%1], 16;" :: "r"(dst), "l"(src) : "memory");
}

__device__ __forceinline__ void group_sync(unsigned* bar, unsigned target) {
    __syncthreads();
    if (threadIdx.x == 0) {
        __threadfence();                 // release
        atomicAdd(bar, 1u);
        while (*(volatile unsigned*)bar < target) { }
        __threadfence();                 // acquire
    }
    __syncthreads();
}

__global__ void init_kernel() { g_bars[threadIdx.x] = 0u; }

// ----------------------------------------------------------------------------
// Kernel 1: input projections (all 3 fused; which = blockIdx.z)
// ----------------------------------------------------------------------------
__global__ __launch_bounds__(256) void proj_kernel(
    const float* __restrict__ X,
    const float* __restrict__ Wi, const float* __restrict__ bi,
    const float* __restrict__ Wc, const float* __restrict__ bc,
    const float* __restrict__ Wo, const float* __restrict__ bo)
{
    __shared__ float A_s[128 * 36];
    __shared__ float B_s[64 * 36];

    const int which = blockIdx.z;
    float* __restrict__ Y = (which == 0) ? g_Xi : (which == 1) ? g_Xc : g_Xo;
    const float* __restrict__ W    = (which == 0) ? Wi : (which == 1) ? Wc : Wo;
    const float* __restrict__ bias = (which == 0) ? bi : (which == 1) ? bc : bo;

    const int tid  = threadIdx.x;
    const int lane = tid & 31;
    const int wid  = tid >> 5;
    const int gid  = lane >> 2;
    const int t4   = lane & 3;
    const int wm   = wid & 3;
    const int wn   = wid >> 2;
    const int bm   = blockIdx.x;
    const int bn   = blockIdx.y;

    const float* Xp = X + (size_t)bm * 128 * 512;
    const float* Wp = W + (size_t)bn * 64 * 512;

    float acc[2][4][4] = {};

    for (int kc = 0; kc < 16; ++kc) {
        __syncthreads();
        #pragma unroll
        for (int p = 0; p < 4; ++p) {
            int r  = (tid >> 3) + p * 32;
            int c4 = (tid & 7) << 2;
            float4 v = *(const float4*)(Xp + (size_t)r * 512 + kc * 32 + c4);
            v.x = tf32r(v.x); v.y = tf32r(v.y); v.z = tf32r(v.z); v.w = tf32r(v.w);
            *(float4*)&A_s[r * 36 + c4] = v;
        }
        #pragma unroll
        for (int p = 0; p < 2; ++p) {
            int r  = (tid >> 3) + p * 32;
            int c4 = (tid & 7) << 2;
            float4 v = *(const float4*)(Wp + (size_t)r * 512 + kc * 32 + c4);
            v.x = tf32r(v.x); v.y = tf32r(v.y); v.z = tf32r(v.z); v.w = tf32r(v.w);
            *(float4*)&B_s[r * 36 + c4] = v;
        }
        __syncthreads();

        #pragma unroll
        for (int k8 = 0; k8 < 4; ++k8) {
            uint32_t aF[2][4], bF[4][2];
            const int ka = k8 * 8 + t4;
            #pragma unroll
            for (int mt2 = 0; mt2 < 2; ++mt2) {
                int ar = (wm * 32 + mt2 * 16 + gid) * 36 + ka;
                aF[mt2][0] = f2u(A_s[ar]);
                aF[mt2][1] = f2u(A_s[ar + 8 * 36]);
                aF[mt2][2] = f2u(A_s[ar + 4]);
                aF[mt2][3] = f2u(A_s[ar + 8 * 36 + 4]);
            }
            #pragma unroll
            for (int nt2 = 0; nt2 < 4; ++nt2) {
                int br = (wn * 32 + nt2 * 8 + gid) * 36 + ka;
                bF[nt2][0] = f2u(B_s[br]);
                bF[nt2][1] = f2u(B_s[br + 4]);
            }
            #pragma unroll
            for (int mt2 = 0; mt2 < 2; ++mt2)
                #pragma unroll
                for (int nt2 = 0; nt2 < 4; ++nt2)
                    mma8(acc[mt2][nt2], aF[mt2], bF[nt2]);
        }
    }

    #pragma unroll
    for (int mt2 = 0; mt2 < 2; ++mt2) {
        #pragma unroll
        for (int nt2 = 0; nt2 < 4; ++nt2) {
            int m = bm * 128 + wm * 32 + mt2 * 16 + gid;
            int n = bn * 64 + wn * 32 + nt2 * 8 + 2 * t4;
            float b0 = bias[n], b1 = bias[n + 1];
            Y[(size_t)m * 512 + n]           = acc[mt2][nt2][0] + b0;
            Y[(size_t)m * 512 + n + 1]       = acc[mt2][nt2][1] + b1;
            Y[(size_t)(m + 8) * 512 + n]     = acc[mt2][nt2][2] + b0;
            Y[(size_t)(m + 8) * 512 + n + 1] = acc[mt2][nt2][3] + b1;
        }
    }
}

// ----------------------------------------------------------------------------
// Kernel 2: persistent recurrence — 4 independent groups of 32 blocks.
// Group g owns batches [16g, 16g+16). Block j in group owns logical h-cols
// [16j, 16j+16) for all 4 gates (Z = 16 batches x 64 gate-cols).
// Per step: stage h slice (16x512, 32 KB) via pipelined cp.async, tf32 MMA,
// gates, write h, group-local barrier.
// ----------------------------------------------------------------------------
__global__ __launch_bounds__(256, 1) void lstm_rec_kernel(
    const float* __restrict__ Ui, const float* __restrict__ Uf,
    const float* __restrict__ Uc, const float* __restrict__ Uo,
    const float* __restrict__ bUf, const float* __restrict__ bUc,
    const float* __restrict__ bUo, float* __restrict__ out)
{
    extern __shared__ float dyn[];
    float* U_s = dyn;                    // 64 x USTR  (132 KB)
    float* h_s = dyn + 64 * USTR;        // 16 x HSTR  (33 KB)
    __shared__ float Z_s[NB * 64];       // 4 KB
    __shared__ float c_s[256];

    const int tid  = threadIdx.x;
    const int lane = tid & 31;
    const int wid  = tid >> 5;           // n-tile: warp covers 8 gate-cols
    const int gid  = lane >> 2;
    const int t4   = lane & 3;
    const int bx   = blockIdx.x;
    const int grp  = bx >> 5;            // 0..3
    const int j    = bx & 31;            // block-in-group
    const int gb0  = grp * NB;           // first global batch of group
    const int nb0  = j * NC;             // first logical h-col of block

    unsigned* bar = &g_bars[grp * 32];

    // Elementwise mapping: thread -> (local batch, local col)
    const int lb = tid >> 4;             // 0..15
    const int lc = tid & 15;             // 0..15

    // Load U slice, permuted per 32-col chunk.
    // U_s rows: 0-15 gate i (cols nb0..nb0+15), 16-31 f, 32-47 c, 48-63 o.
    for (int idx = tid; idx < 64 * 512; idx += 256) {
        int r = idx >> 9;
        int k = idx & 511;
        int g = r >> 4;
        int n = nb0 + (r & 15);
        const float* Up = (g == 0) ? Ui : (g == 1) ? Uf : (g == 2) ? Uc : Uo;
        int pk = (k & ~31) + (k & 3) * 8 + ((k >> 2) & 7);
        U_s[r * USTR + pk] = tf32r(Up[(size_t)n * 512 + k]);
    }
    c_s[tid] = 0.0f;

    // Zero this block's h cells (permuted column position)
    const int ncol = nb0 + lc;
    const int pcol = (ncol & ~31) + (ncol & 3) * 8 + ((ncol >> 2) & 7);
    g_h[(gb0 + lb) * 512 + pcol] = 0.0f;

    const float bUf_r = bUf[ncol];
    const float bUc_r = bUc[ncol];
    const float bUo_r = bUo[ncol];

    unsigned bar_t = GBLKS;
    group_sync(bar, bar_t);              // group's h zeros visible

    const size_t btd = (size_t)NTOK * DD;
    size_t xidx = ((size_t)(gb0 + lb) * TT) * DD + ncol;   // t = 0
    float xiv = __ldcs(&g_Xi[xidx]);
    float xcv = __ldcs(&g_Xc[xidx]);
    float xov = __ldcs(&g_Xo[xidx]);

    const uint32_t hbase = (uint32_t)__cvta_generic_to_shared(h_s);
    // cp.async map: per commit-group p (cols 128p..128p+128): f = tid*2+{0,1}
    const int cprow = (tid * 2) >> 5;          // 0..15
    const int cpc4  = (tid * 2) & 31;          // float4 idx within 32

    const float* Arow0 = h_s + gid * HSTR + t4 * 8;
    const float* Arow1 = Arow0 + 8 * HSTR;
    const float* Brow  = U_s + (wid * 8 + gid) * USTR + t4 * 8;

    for (int t = 0; t < TT; ++t) {
        // Issue h staging: 4 commit groups x 4 chunks (128 cols each)
        #pragma unroll
        for (int p = 0; p < 4; ++p) {
            const float* src = g_h + (gb0 + cprow) * 512 + p * 128 + cpc4 * 4;
            uint32_t     dst = hbase + (uint32_t)(cprow * HSTR + p * 128 + cpc4 * 4) * 4;
            cp16(dst, src);
            cp16(dst + 16, src + 4);
            asm volatile("cp.async.commit_group;" ::: "memory");
        }

        // Prefetch next-step x while MMAs run
        float xiv_n = 0.f, xcv_n = 0.f, xov_n = 0.f;
        if (t + 1 < TT) {
            xiv_n = __ldcs(&g_Xi[xidx + DD]);
            xcv_n = __ldcs(&g_Xc[xidx + DD]);
            xov_n = __ldcs(&g_Xo[xidx + DD]);
        }

        float acc0[4] = {}, acc1[4] = {};

        #define COMPUTE_KC(kc) { \
            const float4 alo0 = *(const float4*)(Arow0 + (kc) * 32); \
            const float4 alo1 = *(const float4*)(Arow0 + (kc) * 32 + 4); \
            const float4 ahi0 = *(const float4*)(Arow1 + (kc) * 32); \
            const float4 ahi1 = *(const float4*)(Arow1 + (kc) * 32 + 4); \
            const float4 bv0  = *(const float4*)(Brow  + (kc) * 32); \
            const float4 bv1  = *(const float4*)(Brow  + (kc) * 32 + 4); \
            uint32_t a[4], b[2]; \
            a[0]=f2u(alo0.x); a[1]=f2u(ahi0.x); a[2]=f2u(alo0.y); a[3]=f2u(ahi0.y); \
            b[0]=f2u(bv0.x);  b[1]=f2u(bv0.y);  mma8(acc0, a, b); \
            a[0]=f2u(alo0.z); a[1]=f2u(ahi0.z); a[2]=f2u(alo0.w); a[3]=f2u(ahi0.w); \
            b[0]=f2u(bv0.z);  b[1]=f2u(bv0.w);  mma8(acc1, a, b); \
            a[0]=f2u(alo1.x); a[1]=f2u(ahi1.x); a[2]=f2u(alo1.y); a[3]=f2u(ahi1.y); \
            b[0]=f2u(bv1.x);  b[1]=f2u(bv1.y);  mma8(acc0, a, b); \
            a[0]=f2u(alo1.z); a[1]=f2u(ahi1.z); a[2]=f2u(alo1.w); a[3]=f2u(ahi1.w); \
            b[0]=f2u(bv1.z);  b[1]=f2u(bv1.w);  mma8(acc1, a, b); \
        }

        asm volatile("cp.async.wait_group 3;" ::: "memory");
        __syncthreads();
        COMPUTE_KC(0)  COMPUTE_KC(1)  COMPUTE_KC(2)  COMPUTE_KC(3)
        asm volatile("cp.async.wait_group 2;" ::: "memory");
        __syncthreads();
        COMPUTE_KC(4)  COMPUTE_KC(5)  COMPUTE_KC(6)  COMPUTE_KC(7)
        asm volatile("cp.async.wait_group 1;" ::: "memory");
        __syncthreads();
        COMPUTE_KC(8)  COMPUTE_KC(9)  COMPUTE_KC(10) COMPUTE_KC(11)
        asm volatile("cp.async.wait_group 0;" ::: "memory");
        __syncthreads();
        COMPUTE_KC(12) COMPUTE_KC(13) COMPUTE_KC(14) COMPUTE_KC(15)

        #undef COMPUTE_KC

        // Write Z (16 x 64): warp wid covers cols wid*8..wid*8+8
        const int zc = wid * 8 + 2 * t4;
        Z_s[gid * 64 + zc]           = acc0[0] + acc1[0];
        Z_s[gid * 64 + zc + 1]       = acc0[1] + acc1[1];
        Z_s[(gid + 8) * 64 + zc]     = acc0[2] + acc1[2];
        Z_s[(gid + 8) * 64 + zc + 1] = acc0[3] + acc1[3];
        __syncthreads();

        // Elementwise gates: thread -> (lb, lc)
        const float zi  = Z_s[lb * 64 + lc];
        const float zf  = Z_s[lb * 64 + 16 + lc];
        const float zcv = Z_s[lb * 64 + 32 + lc];
        const float zo  = Z_s[lb * 64 + 48 + lc];

        const float ig = sigf(xiv + zi);
        const float fg = sigf(xiv + zf + bUf_r);          // reference quirk: uses xi
        const float cn = fg * c_s[tid] + ig * tanhf(xcv + zcv + bUc_r);
        const float og = sigf(xov + zo + bUo_r);
        const float hn = og * tanhf(cn);

        c_s[tid] = cn;
        g_h[(gb0 + lb) * 512 + pcol] = tf32r(hn);   // permuted store
        out[xidx]       = hn;                        // H
        out[btd + xidx] = cn;                        // C

        xiv = xiv_n; xcv = xcv_n; xov = xov_n;
        xidx += DD;

        bar_t += GBLKS;
        if (t + 1 < TT) group_sync(bar, bar_t);      // skip final barrier
    }
}

// ----------------------------------------------------------------------------
// Launch
// ----------------------------------------------------------------------------
extern "C" void kernel_launch(void* const* d_in, const int* in_sizes, int n_in,
                              void* d_out, int out_size) {
    (void)in_sizes; (void)n_in; (void)out_size;

    const float* X   = (const float*)d_in[0];
    const float* Wi  = (const float*)d_in[1];
    const float* bi  = (const float*)d_in[2];
    // d_in[3]=Wf, d_in[4]=bf unused (reference computes Xf but never uses it)
    const float* Wc  = (const float*)d_in[5];
    const float* bc  = (const float*)d_in[6];
    const float* Wo  = (const float*)d_in[7];
    const float* bo  = (const float*)d_in[8];
    const float* Ui  = (const float*)d_in[9];
    const float* Uf  = (const float*)d_in[10];
    const float* bUf = (const float*)d_in[11];
    const float* Uc  = (const float*)d_in[12];
    const float* bUc = (const float*)d_in[13];
    const float* Uo  = (const float*)d_in[14];
    const float* bUo = (const float*)d_in[15];
    float* out = (float*)d_out;

    static const int dyn_smem = (64 + 16) * USTR * 4;   // 165,120 B
    cudaFuncSetAttribute(lstm_rec_kernel,
                         cudaFuncAttributeMaxDynamicSharedMemorySize, dyn_smem);

    init_kernel<<<1, NGRP * 32>>>();

    dim3 pgrid(NTOK / 128, 8, 3);
    proj_kernel<<<pgrid, 256>>>(X, Wi, bi, Wc, bc, Wo, bo);

    lstm_rec_kernel<<<NGRP * GBLKS, 256, dyn_smem>>>(Ui, Uf, Uc, Uo, bUf, bUc, bUo, out);
}

// round 6
// speedup vs baseline: 2.3313x; 1.0435x over previous
#include <cuda_runtime.h>
#include <cstdint>

// Problem dims
#define BB 64
#define TT 512
#define DD 512
#define NTOK (BB * TT)                 // 32768

// Recurrence decomposition: 4 independent batch-groups x 32 blocks
#define NGRP  4
#define GBLKS 32                        // blocks per group
#define NB    16                        // batches per group
#define NC    16                        // logical h-cols per block (x4 gates = 64)

#define USTR 516                        // SMEM row strides (== 4 mod 32 -> conflict-free LDS.128)
#define HSTR 516

// ----------------------------------------------------------------------------
// Scratch (device globals — no allocations allowed)
// ----------------------------------------------------------------------------
__device__ float g_Xi[16777216];
__device__ float g_Xc[16777216];
__device__ float g_Xo[16777216];
__device__ float g_h[2][BB * DD];       // DOUBLE-BUFFERED, COLUMN-PERMUTED per 32-col chunk
__device__ unsigned g_flags[NGRP * GBLKS * 32];  // flag (grp,j) at [(grp*32+j)*32], 128B apart

// ----------------------------------------------------------------------------
// Helpers
// ----------------------------------------------------------------------------
__device__ __forceinline__ float tf32r(float x) {
    uint32_t u;
    asm("cvt.rna.tf32.f32 %0, %1;" : "=r"(u) : "f"(x));
    return __uint_as_float(u);
}
#define f2u __float_as_uint

__device__ __forceinline__ void mma8(float (&d)[4], const uint32_t a[4], const uint32_t b[2]) {
    asm volatile(
        "mma.sync.aligned.m16n8k8.row.col.f32.tf32.tf32.f32 "
        "{%0,%1,%2,%3}, {%4,%5,%6,%7}, {%8,%9}, {%0,%1,%2,%3};\n"
        : "+f"(d[0]), "+f"(d[1]), "+f"(d[2]), "+f"(d[3])
        : "r"(a[0]), "r"(a[1]), "r"(a[2]), "r"(a[3]), "r"(b[0]), "r"(b[1]));
}

__device__ __forceinline__ float sigf(float x) {
    return 1.0f / (1.0f + __expf(-x));
}

__device__ __forceinline__ void cp16(uint32_t dst, const void* src) {
    asm volatile("cp.async.cg.shared.global [%0], [%1], 16;" :: "r"(dst), "l"(src) : "memory");
}

__device__ __forceinline__ unsigned ldacq(const unsigned* p) {
    unsigned v;
    asm volatile("ld.acquire.gpu.global.u32 %0, [%1];" : "=r"(v) : "l"(p) : "memory");
    return v;
}

__device__ __forceinline__ void strelax(unsigned* p, unsigned v) {
    asm volatile("st.relaxed.gpu.global.u32 [%0], %1;" :: "l"(p), "r"(v) : "memory");
}

// Fast path: one acquire load. Slow path: nanosleep-backoff spin.
__device__ __forceinline__ void wait_flag(const unsigned* p, unsigned tv) {
    if (ldacq(p) >= tv) return;
    do { __nanosleep(32); } while (ldacq(p) < tv);
}

__global__ void init_kernel() {
    // grid 128 x 256 = 32768 threads
    int tid = blockIdx.x * blockDim.x + threadIdx.x;
    float* h = &g_h[0][0];
    h[tid]         = 0.0f;    // buf0 (h(0) = zeros)
    h[tid + 32768] = 0.0f;    // buf1
    if (tid < NGRP * GBLKS * 32) g_flags[tid] = 0u;   // flag=0 <=> h(0) published
}

// ----------------------------------------------------------------------------
// Kernel 1: input projections (all 3 fused; which = blockIdx.z)
// ----------------------------------------------------------------------------
__global__ __launch_bounds__(256) void proj_kernel(
    const float* __restrict__ X,
    const float* __restrict__ Wi, const float* __restrict__ bi,
    const float* __restrict__ Wc, const float* __restrict__ bc,
    const float* __restrict__ Wo, const float* __restrict__ bo)
{
    __shared__ float A_s[128 * 36];
    __shared__ float B_s[64 * 36];

    const int which = blockIdx.z;
    float* __restrict__ Y = (which == 0) ? g_Xi : (which == 1) ? g_Xc : g_Xo;
    const float* __restrict__ W    = (which == 0) ? Wi : (which == 1) ? Wc : Wo;
    const float* __restrict__ bias = (which == 0) ? bi : (which == 1) ? bc : bo;

    const int tid  = threadIdx.x;
    const int lane = tid & 31;
    const int wid  = tid >> 5;
    const int gid  = lane >> 2;
    const int t4   = lane & 3;
    const int wm   = wid & 3;
    const int wn   = wid >> 2;
    const int bm   = blockIdx.x;
    const int bn   = blockIdx.y;

    const float* Xp = X + (size_t)bm * 128 * 512;
    const float* Wp = W + (size_t)bn * 64 * 512;

    float acc[2][4][4] = {};

    for (int kc = 0; kc < 16; ++kc) {
        __syncthreads();
        #pragma unroll
        for (int p = 0; p < 4; ++p) {
            int r  = (tid >> 3) + p * 32;
            int c4 = (tid & 7) << 2;
            float4 v = *(const float4*)(Xp + (size_t)r * 512 + kc * 32 + c4);
            v.x = tf32r(v.x); v.y = tf32r(v.y); v.z = tf32r(v.z); v.w = tf32r(v.w);
            *(float4*)&A_s[r * 36 + c4] = v;
        }
        #pragma unroll
        for (int p = 0; p < 2; ++p) {
            int r  = (tid >> 3) + p * 32;
            int c4 = (tid & 7) << 2;
            float4 v = *(const float4*)(Wp + (size_t)r * 512 + kc * 32 + c4);
            v.x = tf32r(v.x); v.y = tf32r(v.y); v.z = tf32r(v.z); v.w = tf32r(v.w);
            *(float4*)&B_s[r * 36 + c4] = v;
        }
        __syncthreads();

        #pragma unroll
        for (int k8 = 0; k8 < 4; ++k8) {
            uint32_t aF[2][4], bF[4][2];
            const int ka = k8 * 8 + t4;
            #pragma unroll
            for (int mt2 = 0; mt2 < 2; ++mt2) {
                int ar = (wm * 32 + mt2 * 16 + gid) * 36 + ka;
                aF[mt2][0] = f2u(A_s[ar]);
                aF[mt2][1] = f2u(A_s[ar + 8 * 36]);
                aF[mt2][2] = f2u(A_s[ar + 4]);
                aF[mt2][3] = f2u(A_s[ar + 8 * 36 + 4]);
            }
            #pragma unroll
            for (int nt2 = 0; nt2 < 4; ++nt2) {
                int br = (wn * 32 + nt2 * 8 + gid) * 36 + ka;
                bF[nt2][0] = f2u(B_s[br]);
                bF[nt2][1] = f2u(B_s[br + 4]);
            }
            #pragma unroll
            for (int mt2 = 0; mt2 < 2; ++mt2)
                #pragma unroll
                for (int nt2 = 0; nt2 < 4; ++nt2)
                    mma8(acc[mt2][nt2], aF[mt2], bF[nt2]);
        }
    }

    #pragma unroll
    for (int mt2 = 0; mt2 < 2; ++mt2) {
        #pragma unroll
        for (int nt2 = 0; nt2 < 4; ++nt2) {
            int m = bm * 128 + wm * 32 + mt2 * 16 + gid;
            int n = bn * 64 + wn * 32 + nt2 * 8 + 2 * t4;
            float b0 = bias[n], b1 = bias[n + 1];
            Y[(size_t)m * 512 + n]           = acc[mt2][nt2][0] + b0;
            Y[(size_t)m * 512 + n + 1]       = acc[mt2][nt2][1] + b1;
            Y[(size_t)(m + 8) * 512 + n]     = acc[mt2][nt2][2] + b0;
            Y[(size_t)(m + 8) * 512 + n + 1] = acc[mt2][nt2][3] + b1;
        }
    }
}

// ----------------------------------------------------------------------------
// Kernel 2: persistent recurrence — 4 independent groups of 32 blocks.
// Sync: per-producer monotone flags (128B-spaced lines) + double-buffered h.
//   flag_j = v  <=>  block j has written h(v) (and finished reading h(v-1)).
// Consumer iteration t: threads 0..31 each poll ONE distinct producer flag
// (>= t), then __syncthreads (block-scope fence transfers the acquire),
// then stage h from g_h[t&1] via pipelined cp.async.cg (L2-read path).
// Write h(t+1) to g_h[(t+1)&1]; publish flag = t+1 after a threadfence.
// WAR-safe: all 32 flags >= t observed before any h(t+1) store.
// Deadlock-free: publish is unconditional every step.
// ----------------------------------------------------------------------------
__global__ __launch_bounds__(256, 1) void lstm_rec_kernel(
    const float* __restrict__ Ui, const float* __restrict__ Uf,
    const float* __restrict__ Uc, const float* __restrict__ Uo,
    const float* __restrict__ bUf, const float* __restrict__ bUc,
    const float* __restrict__ bUo, float* __restrict__ out)
{
    extern __shared__ float dyn[];
    float* U_s = dyn;                    // 64 x USTR  (132 KB)
    float* h_s = dyn + 64 * USTR;        // 16 x HSTR  (33 KB)
    __shared__ float Z_s[NB * 64];       // 4 KB
    __shared__ float c_s[256];

    const int tid  = threadIdx.x;
    const int lane = tid & 31;
    const int wid  = tid >> 5;           // n-tile: warp covers 8 gate-cols
    const int gid  = lane >> 2;
    const int t4   = lane & 3;
    const int bx   = blockIdx.x;
    const int grp  = bx >> 5;            // 0..3
    const int j    = bx & 31;            // block-in-group
    const int gb0  = grp * NB;           // first global batch of group
    const int nb0  = j * NC;             // first logical h-col of block

    unsigned* fbase  = g_flags + grp * GBLKS * 32;
    unsigned* myflag = fbase + j * 32;

    // Elementwise mapping: thread -> (local batch, local col)
    const int lb = tid >> 4;             // 0..15
    const int lc = tid & 15;             // 0..15

    // Load U slice, permuted per 32-col chunk.
    for (int idx = tid; idx < 64 * 512; idx += 256) {
        int r = idx >> 9;
        int k = idx & 511;
        int g = r >> 4;
        int n = nb0 + (r & 15);
        const float* Up = (g == 0) ? Ui : (g == 1) ? Uf : (g == 2) ? Uc : Uo;
        int pk = (k & ~31) + (k & 3) * 8 + ((k >> 2) & 7);
        U_s[r * USTR + pk] = tf32r(Up[(size_t)n * 512 + k]);
    }
    c_s[tid] = 0.0f;

    const int ncol = nb0 + lc;
    const int pcol = (ncol & ~31) + (ncol & 3) * 8 + ((ncol >> 2) & 7);

    const float bUf_r = bUf[ncol];
    const float bUc_r = bUc[ncol];
    const float bUo_r = bUo[ncol];

    const size_t btd = (size_t)NTOK * DD;
    size_t xidx = ((size_t)(gb0 + lb) * TT) * DD + ncol;   // t = 0
    float xiv = __ldcs(&g_Xi[xidx]);
    float xcv = __ldcs(&g_Xc[xidx]);
    float xov = __ldcs(&g_Xo[xidx]);

    const uint32_t hbase = (uint32_t)__cvta_generic_to_shared(h_s);
    // cp.async map: rows cprow / cprow+8; c4 = float4 col within 128-col group
    const int cprow = tid >> 5;                // 0..7
    const int c4    = tid & 31;                // 0..31

    const float* Arow0 = h_s + gid * HSTR + t4 * 8;
    const float* Arow1 = Arow0 + 8 * HSTR;
    const float* Brow  = U_s + (wid * 8 + gid) * USTR + t4 * 8;

    __syncthreads();    // U_s / c_s ready (h(0) zeroed by init_kernel)

    for (int t = 0; t < TT; ++t) {
        const unsigned tv = (unsigned)t;
        const float* hbuf = g_h[t & 1];

        // Gate: 32 threads poll 32 distinct producer flag lines in parallel.
        if (tid < GBLKS) wait_flag(fbase + tid * 32, tv);
        __syncthreads();

        // Issue h staging: 4 commit groups of 128 cols each
        #pragma unroll
        for (int p = 0; p < 4; ++p) {
            const float* src = hbuf + (gb0 + cprow) * 512 + p * 128 + c4 * 4;
            uint32_t     dst = hbase + (uint32_t)(cprow * HSTR + p * 128 + c4 * 4) * 4;
            cp16(dst, src);
            cp16(dst + (uint32_t)(8 * HSTR) * 4, src + 8 * 512);
            asm volatile("cp.async.commit_group;" ::: "memory");
        }

        // Prefetch next-step x while MMAs run
        float xiv_n = 0.f, xcv_n = 0.f, xov_n = 0.f;
        if (t + 1 < TT) {
            xiv_n = __ldcs(&g_Xi[xidx + DD]);
            xcv_n = __ldcs(&g_Xc[xidx + DD]);
            xov_n = __ldcs(&g_Xo[xidx + DD]);
        }

        float acc0[4] = {}, acc1[4] = {};

        #define COMPUTE_KC(kc) { \
            const float4 alo0 = *(const float4*)(Arow0 + (kc) * 32); \
            const float4 alo1 = *(const float4*)(Arow0 + (kc) * 32 + 4); \
            const float4 ahi0 = *(const float4*)(Arow1 + (kc) * 32); \
            const float4 ahi1 = *(const float4*)(Arow1 + (kc) * 32 + 4); \
            const float4 bv0  = *(const float4*)(Brow  + (kc) * 32); \
            const float4 bv1  = *(const float4*)(Brow  + (kc) * 32 + 4); \
            uint32_t a[4], b[2]; \
            a[0]=f2u(alo0.x); a[1]=f2u(ahi0.x); a[2]=f2u(alo0.y); a[3]=f2u(ahi0.y); \
            b[0]=f2u(bv0.x);  b[1]=f2u(bv0.y);  mma8(acc0, a, b); \
            a[0]=f2u(alo0.z); a[1]=f2u(ahi0.z); a[2]=f2u(alo0.w); a[3]=f2u(ahi0.w); \
            b[0]=f2u(bv0.z);  b[1]=f2u(bv0.w);  mma8(acc1, a, b); \
            a[0]=f2u(alo1.x); a[1]=f2u(ahi1.x); a[2]=f2u(alo1.y); a[3]=f2u(ahi1.y); \
            b[0]=f2u(bv1.x);  b[1]=f2u(bv1.y);  mma8(acc0, a, b); \
            a[0]=f2u(alo1.z); a[1]=f2u(ahi1.z); a[2]=f2u(alo1.w); a[3]=f2u(ahi1.w); \
            b[0]=f2u(bv1.z);  b[1]=f2u(bv1.w);  mma8(acc1, a, b); \
        }

        asm volatile("cp.async.wait_group 3;" ::: "memory");
        __syncthreads();
        COMPUTE_KC(0)  COMPUTE_KC(1)  COMPUTE_KC(2)  COMPUTE_KC(3)
        asm volatile("cp.async.wait_group 2;" ::: "memory");
        __syncthreads();
        COMPUTE_KC(4)  COMPUTE_KC(5)  COMPUTE_KC(6)  COMPUTE_KC(7)
        asm volatile("cp.async.wait_group 1;" ::: "memory");
        __syncthreads();
        COMPUTE_KC(8)  COMPUTE_KC(9)  COMPUTE_KC(10) COMPUTE_KC(11)
        asm volatile("cp.async.wait_group 0;" ::: "memory");
        __syncthreads();
        COMPUTE_KC(12) COMPUTE_KC(13) COMPUTE_KC(14) COMPUTE_KC(15)

        #undef COMPUTE_KC

        // Write Z (16 x 64): warp wid covers cols wid*8..wid*8+8
        const int zc = wid * 8 + 2 * t4;
        Z_s[gid * 64 + zc]           = acc0[0] + acc1[0];
        Z_s[gid * 64 + zc + 1]       = acc0[1] + acc1[1];
        Z_s[(gid + 8) * 64 + zc]     = acc0[2] + acc1[2];
        Z_s[(gid + 8) * 64 + zc + 1] = acc0[3] + acc1[3];
        __syncthreads();

        // Elementwise gates: thread -> (lb, lc)
        const float zi  = Z_s[lb * 64 + lc];
        const float zf  = Z_s[lb * 64 + 16 + lc];
        const float zcv = Z_s[lb * 64 + 32 + lc];
        const float zo  = Z_s[lb * 64 + 48 + lc];

        const float ig = sigf(xiv + zi);
        const float fg = sigf(xiv + zf + bUf_r);          // reference quirk: uses xi
        const float cn = fg * c_s[tid] + ig * tanhf(xcv + zcv + bUc_r);
        const float og = sigf(xov + zo + bUo_r);
        const float hn = og * tanhf(cn);

        c_s[tid] = cn;
        g_h[(t + 1) & 1][(gb0 + lb) * 512 + pcol] = tf32r(hn);   // h(t+1), permuted
        __stcs(&out[xidx], hn);                                   // H (streaming)
        __stcs(&out[btd + xidx], cn);                             // C (streaming)

        xiv = xiv_n; xcv = xcv_n; xov = xov_n;
        xidx += DD;

        // Publish flag = t+1 (after all threads' h stores)
        __syncthreads();
        if (tid == 0) {
            __threadfence();
            strelax(myflag, (unsigned)(t + 1));
        }
    }
}

// ----------------------------------------------------------------------------
// Launch
// ----------------------------------------------------------------------------
extern "C" void kernel_launch(void* const* d_in, const int* in_sizes, int n_in,
                              void* d_out, int out_size) {
    (void)in_sizes; (void)n_in; (void)out_size;

    const float* X   = (const float*)d_in[0];
    const float* Wi  = (const float*)d_in[1];
    const float* bi  = (const float*)d_in[2];
    // d_in[3]=Wf, d_in[4]=bf unused (reference computes Xf but never uses it)
    const float* Wc  = (const float*)d_in[5];
    const float* bc  = (const float*)d_in[6];
    const float* Wo  = (const float*)d_in[7];
    const float* bo  = (const float*)d_in[8];
    const float* Ui  = (const float*)d_in[9];
    const float* Uf  = (const float*)d_in[10];
    const float* bUf = (const float*)d_in[11];
    const float* Uc  = (const float*)d_in[12];
    const float* bUc = (const float*)d_in[13];
    const float* Uo  = (const float*)d_in[14];
    const float* bUo = (const float*)d_in[15];
    float* out = (float*)d_out;

    static const int dyn_smem = (64 + 16) * USTR * 4;   // 165,120 B
    cudaFuncSetAttribute(lstm_rec_kernel,
                         cudaFuncAttributeMaxDynamicSharedMemorySize, dyn_smem);

    init_kernel<<<128, 256>>>();

    dim3 pgrid(NTOK / 128, 8, 3);
    proj_kernel<<<pgrid, 256>>>(X, Wi, bi, Wc, bc, Wo, bo);

    lstm_rec_kernel<<<NGRP * GBLKS, 256, dyn_smem>>>(Ui, Uf, Uc, Uo, bUf, bUc, bUo, out);
}

// round 7
// speedup vs baseline: 3.0030x; 1.2882x over previous
#include <cuda_runtime.h>
#include <cuda_fp16.h>
#include <cstdint>

// Problem dims
#define BB 64
#define TT 512
#define DD 512
#define NTOK (BB * TT)                 // 32768

// Recurrence decomposition: 4 independent batch-groups x 32 blocks
#define NGRP  4
#define GBLKS 32                        // blocks per group
#define NB    16                        // batches per group
#define NC    16                        // logical h-cols per block (x4 gates = 64)

#define USTR 516                        // proj SMEM stride (fp32)
#define HSTRH 528                       // recurrence SMEM stride in HALVES (1056B; 264 words == 8 mod 32)

// ----------------------------------------------------------------------------
// Scratch (device globals — no allocations allowed)
// ----------------------------------------------------------------------------
__device__ float  g_Xi[16777216];
__device__ float  g_Xc[16777216];
__device__ float  g_Xo[16777216];
__device__ __half g_h16[2][BB * DD];    // DOUBLE-BUFFERED fp16 h, column-permuted per 16-col chunk
__device__ unsigned g_flags[NGRP * GBLKS * 32];  // flag (grp,j) at [(grp*32+j)*32], 128B apart

// ----------------------------------------------------------------------------
// Helpers
// ----------------------------------------------------------------------------
__device__ __forceinline__ float tf32r(float x) {
    uint32_t u;
    asm("cvt.rna.tf32.f32 %0, %1;" : "=r"(u) : "f"(x));
    return __uint_as_float(u);
}
#define f2u __float_as_uint

// tf32 m16n8k8 (proj kernel)
__device__ __forceinline__ void mma8(float (&d)[4], const uint32_t a[4], const uint32_t b[2]) {
    asm volatile(
        "mma.sync.aligned.m16n8k8.row.col.f32.tf32.tf32.f32 "
        "{%0,%1,%2,%3}, {%4,%5,%6,%7}, {%8,%9}, {%0,%1,%2,%3};\n"
        : "+f"(d[0]), "+f"(d[1]), "+f"(d[2]), "+f"(d[3])
        : "r"(a[0]), "r"(a[1]), "r"(a[2]), "r"(a[3]), "r"(b[0]), "r"(b[1]));
}

// f16 m16n8k16 (recurrence kernel), fp32 accum
__device__ __forceinline__ void mma16h(float (&d)[4], uint32_t a0, uint32_t a1,
                                       uint32_t a2, uint32_t a3, uint32_t b0, uint32_t b1) {
    asm volatile(
        "mma.sync.aligned.m16n8k16.row.col.f32.f16.f16.f32 "
        "{%0,%1,%2,%3}, {%4,%5,%6,%7}, {%8,%9}, {%0,%1,%2,%3};\n"
        : "+f"(d[0]), "+f"(d[1]), "+f"(d[2]), "+f"(d[3])
        : "r"(a0), "r"(a1), "r"(a2), "r"(a3), "r"(b0), "r"(b1));
}

__device__ __forceinline__ float sigf(float x) {
    return 1.0f / (1.0f + __expf(-x));
}

__device__ __forceinline__ void cp16(uint32_t dst, const void* src) {
    asm volatile("cp.async.cg.shared.global [%0], [%1], 16;" :: "r"(dst), "l"(src) : "memory");
}

__device__ __forceinline__ unsigned ldacq(const unsigned* p) {
    unsigned v;
    asm volatile("ld.acquire.gpu.global.u32 %0, [%1];" : "=r"(v) : "l"(p) : "memory");
    return v;
}

__device__ __forceinline__ void strelax(unsigned* p, unsigned v) {
    asm volatile("st.relaxed.gpu.global.u32 [%0], %1;" :: "l"(p), "r"(v) : "memory");
}

__device__ __forceinline__ void wait_flag(const unsigned* p, unsigned tv) {
    if (ldacq(p) >= tv) return;
    do { __nanosleep(32); } while (ldacq(p) < tv);
}

// Within-16 k-permutation: [0,1,8,9, 2,3,10,11, 4,5,12,13, 6,7,14,15]
// so thread t4 (0..3) reads its 4 needed halves {2t4,2t4+1,2t4+8,2t4+9} contiguously.
__device__ __forceinline__ int perm16(int k) {
    int k4 = k & 15;
    return (k & ~15) + ((k4 & 7) >> 1) * 4 + (k4 & 1) + ((k4 >> 3) << 1);
}

__global__ void init_kernel() {
    // grid 128 x 256 = 32768 threads: zero both fp16 h buffers (32768 uint32) + flags
    int tid = blockIdx.x * blockDim.x + threadIdx.x;
    ((uint32_t*)g_h16)[tid] = 0u;
    if (tid < NGRP * GBLKS * 32) g_flags[tid] = 0u;   // flag=0 <=> h(0) published
}

// ----------------------------------------------------------------------------
// Kernel 1: input projections (all 3 fused; which = blockIdx.z) — tf32, unchanged
// ----------------------------------------------------------------------------
__global__ __launch_bounds__(256) void proj_kernel(
    const float* __restrict__ X,
    const float* __restrict__ Wi, const float* __restrict__ bi,
    const float* __restrict__ Wc, const float* __restrict__ bc,
    const float* __restrict__ Wo, const float* __restrict__ bo)
{
    __shared__ float A_s[128 * 36];
    __shared__ float B_s[64 * 36];

    const int which = blockIdx.z;
    float* __restrict__ Y = (which == 0) ? g_Xi : (which == 1) ? g_Xc : g_Xo;
    const float* __restrict__ W    = (which == 0) ? Wi : (which == 1) ? Wc : Wo;
    const float* __restrict__ bias = (which == 0) ? bi : (which == 1) ? bc : bo;

    const int tid  = threadIdx.x;
    const int lane = tid & 31;
    const int wid  = tid >> 5;
    const int gid  = lane >> 2;
    const int t4   = lane & 3;
    const int wm   = wid & 3;
    const int wn   = wid >> 2;
    const int bm   = blockIdx.x;
    const int bn   = blockIdx.y;

    const float* Xp = X + (size_t)bm * 128 * 512;
    const float* Wp = W + (size_t)bn * 64 * 512;

    float acc[2][4][4] = {};

    for (int kc = 0; kc < 16; ++kc) {
        __syncthreads();
        #pragma unroll
        for (int p = 0; p < 4; ++p) {
            int r  = (tid >> 3) + p * 32;
            int c4 = (tid & 7) << 2;
            float4 v = *(const float4*)(Xp + (size_t)r * 512 + kc * 32 + c4);
            v.x = tf32r(v.x); v.y = tf32r(v.y); v.z = tf32r(v.z); v.w = tf32r(v.w);
            *(float4*)&A_s[r * 36 + c4] = v;
        }
        #pragma unroll
        for (int p = 0; p < 2; ++p) {
            int r  = (tid >> 3) + p * 32;
            int c4 = (tid & 7) << 2;
            float4 v = *(const float4*)(Wp + (size_t)r * 512 + kc * 32 + c4);
            v.x = tf32r(v.x); v.y = tf32r(v.y); v.z = tf32r(v.z); v.w = tf32r(v.w);
            *(float4*)&B_s[r * 36 + c4] = v;
        }
        __syncthreads();

        #pragma unroll
        for (int k8 = 0; k8 < 4; ++k8) {
            uint32_t aF[2][4], bF[4][2];
            const int ka = k8 * 8 + t4;
            #pragma unroll
            for (int mt2 = 0; mt2 < 2; ++mt2) {
                int ar = (wm * 32 + mt2 * 16 + gid) * 36 + ka;
                aF[mt2][0] = f2u(A_s[ar]);
                aF[mt2][1] = f2u(A_s[ar + 8 * 36]);
                aF[mt2][2] = f2u(A_s[ar + 4]);
                aF[mt2][3] = f2u(A_s[ar + 8 * 36 + 4]);
            }
            #pragma unroll
            for (int nt2 = 0; nt2 < 4; ++nt2) {
                int br = (wn * 32 + nt2 * 8 + gid) * 36 + ka;
                bF[nt2][0] = f2u(B_s[br]);
                bF[nt2][1] = f2u(B_s[br + 4]);
            }
            #pragma unroll
            for (int mt2 = 0; mt2 < 2; ++mt2)
                #pragma unroll
                for (int nt2 = 0; nt2 < 4; ++nt2)
                    mma8(acc[mt2][nt2], aF[mt2], bF[nt2]);
        }
    }

    #pragma unroll
    for (int mt2 = 0; mt2 < 2; ++mt2) {
        #pragma unroll
        for (int nt2 = 0; nt2 < 4; ++nt2) {
            int m = bm * 128 + wm * 32 + mt2 * 16 + gid;
            int n = bn * 64 + wn * 32 + nt2 * 8 + 2 * t4;
            float b0 = bias[n], b1 = bias[n + 1];
            Y[(size_t)m * 512 + n]           = acc[mt2][nt2][0] + b0;
            Y[(size_t)m * 512 + n + 1]       = acc[mt2][nt2][1] + b1;
            Y[(size_t)(m + 8) * 512 + n]     = acc[mt2][nt2][2] + b0;
            Y[(size_t)(m + 8) * 512 + n + 1] = acc[mt2][nt2][3] + b1;
        }
    }
}

// ----------------------------------------------------------------------------
// Kernel 2: persistent recurrence — fp16 m16n8k16 MMA, fp32 accumulate.
// Protocol identical to R6 (per-producer flags + double-buffered h).
// h and U stored fp16, column-permuted per 16-col chunk so every MMA fragment
// is one 8B LDS. Row stride 528 halves => conflict-free LDS.64.
// ----------------------------------------------------------------------------
__global__ __launch_bounds__(256, 1) void lstm_rec_kernel(
    const float* __restrict__ Ui, const float* __restrict__ Uf,
    const float* __restrict__ Uc, const float* __restrict__ Uo,
    const float* __restrict__ bUf, const float* __restrict__ bUc,
    const float* __restrict__ bUo, float* __restrict__ out)
{
    extern __shared__ __half dynh[];
    __half* U_s = dynh;                    // 64 x HSTRH  (67.6 KB)
    __half* h_s = dynh + 64 * HSTRH;       // 16 x HSTRH  (16.9 KB)
    __shared__ float Z_s[NB * 64];         // 4 KB
    __shared__ float c_s[256];

    const int tid  = threadIdx.x;
    const int lane = tid & 31;
    const int wid  = tid >> 5;           // n-tile: warp covers 8 gate-cols
    const int gid  = lane >> 2;
    const int t4   = lane & 3;
    const int bx   = blockIdx.x;
    const int grp  = bx >> 5;            // 0..3
    const int j    = bx & 31;            // block-in-group
    const int gb0  = grp * NB;           // first global batch of group
    const int nb0  = j * NC;             // first logical h-col of block

    unsigned* fbase  = g_flags + grp * GBLKS * 32;
    unsigned* myflag = fbase + j * 32;

    // Elementwise mapping: thread -> (local batch, local col)
    const int lb = tid >> 4;             // 0..15
    const int lc = tid & 15;             // 0..15

    // Load U slice (fp16, permuted). rows: 0-15 gate i, 16-31 f, 32-47 c, 48-63 o.
    for (int idx = tid; idx < 64 * 512; idx += 256) {
        int r = idx >> 9;
        int k = idx & 511;
        int g = r >> 4;
        int n = nb0 + (r & 15);
        const float* Up = (g == 0) ? Ui : (g == 1) ? Uf : (g == 2) ? Uc : Uo;
        U_s[r * HSTRH + perm16(k)] = __float2half_rn(Up[(size_t)n * 512 + k]);
    }
    c_s[tid] = 0.0f;

    const int ncol  = nb0 + lc;
    const int pcol  = perm16(ncol);       // permuted global h column

    const float bUf_r = bUf[ncol];
    const float bUc_r = bUc[ncol];
    const float bUo_r = bUo[ncol];

    const size_t btd = (size_t)NTOK * DD;
    size_t xidx = ((size_t)(gb0 + lb) * TT) * DD + ncol;   // t = 0
    float xiv = __ldcs(&g_Xi[xidx]);
    float xcv = __ldcs(&g_Xc[xidx]);
    float xov = __ldcs(&g_Xo[xidx]);

    const uint32_t hbase = (uint32_t)__cvta_generic_to_shared(h_s);
    // cp.async map: per 128-col group p: thread t stages 16B of row (t>>4)
    const int cprow = tid >> 4;                // 0..15
    const int cpseg = tid & 15;                // 0..15 (16B segment within 256B row-chunk)

    const __half* Arow0 = h_s + gid * HSTRH + t4 * 4;
    const __half* Arow1 = Arow0 + 8 * HSTRH;
    const __half* Brow  = U_s + (wid * 8 + gid) * HSTRH + t4 * 4;

    __syncthreads();    // U_s / c_s ready (h(0) zeroed by init_kernel)

    for (int t = 0; t < TT; ++t) {
        const unsigned tv = (unsigned)t;
        const __half* hbuf = g_h16[t & 1];

        // Gate: 32 threads poll 32 distinct producer flag lines in parallel.
        if (tid < GBLKS) wait_flag(fbase + tid * 32, tv);
        __syncthreads();

        // Issue h staging: 4 commit groups of 128 cols each (fp16: 256B per row per group)
        #pragma unroll
        for (int p = 0; p < 4; ++p) {
            const __half* src = hbuf + (gb0 + cprow) * 512 + p * 128 + cpseg * 8;
            uint32_t      dst = hbase + (uint32_t)(cprow * HSTRH + p * 128 + cpseg * 8) * 2;
            cp16(dst, src);
            asm volatile("cp.async.commit_group;" ::: "memory");
        }

        // Prefetch next-step x while MMAs run
        float xiv_n = 0.f, xcv_n = 0.f, xov_n = 0.f;
        if (t + 1 < TT) {
            xiv_n = __ldcs(&g_Xi[xidx + DD]);
            xcv_n = __ldcs(&g_Xc[xidx + DD]);
            xov_n = __ldcs(&g_Xo[xidx + DD]);
        }

        float acc0[4] = {}, acc1[4] = {};

        // One f16 MMA per 16-col chunk; 8 chunks per pipeline stage.
        #define COMPUTE_C16(c) { \
            const uint2 a01 = *(const uint2*)(Arow0 + (c) * 16); \
            const uint2 a23 = *(const uint2*)(Arow1 + (c) * 16); \
            const uint2 bb  = *(const uint2*)(Brow  + (c) * 16); \
            if ((c) & 1) mma16h(acc1, a01.x, a23.x, a01.y, a23.y, bb.x, bb.y); \
            else         mma16h(acc0, a01.x, a23.x, a01.y, a23.y, bb.x, bb.y); \
        }
        #define STAGE8(c0) \
            COMPUTE_C16(c0)   COMPUTE_C16(c0+1) COMPUTE_C16(c0+2) COMPUTE_C16(c0+3) \
            COMPUTE_C16(c0+4) COMPUTE_C16(c0+5) COMPUTE_C16(c0+6) COMPUTE_C16(c0+7)

        asm volatile("cp.async.wait_group 3;" ::: "memory");
        __syncthreads();
        STAGE8(0)
        asm volatile("cp.async.wait_group 2;" ::: "memory");
        __syncthreads();
        STAGE8(8)
        asm volatile("cp.async.wait_group 1;" ::: "memory");
        __syncthreads();
        STAGE8(16)
        asm volatile("cp.async.wait_group 0;" ::: "memory");
        __syncthreads();
        STAGE8(24)

        #undef STAGE8
        #undef COMPUTE_C16

        // Write Z (16 x 64): warp wid covers cols wid*8..wid*8+8
        const int zc = wid * 8 + 2 * t4;
        Z_s[gid * 64 + zc]           = acc0[0] + acc1[0];
        Z_s[gid * 64 + zc + 1]       = acc0[1] + acc1[1];
        Z_s[(gid + 8) * 64 + zc]     = acc0[2] + acc1[2];
        Z_s[(gid + 8) * 64 + zc + 1] = acc0[3] + acc1[3];
        __syncthreads();

        // Elementwise gates: thread -> (lb, lc)
        const float zi  = Z_s[lb * 64 + lc];
        const float zf  = Z_s[lb * 64 + 16 + lc];
        const float zcv = Z_s[lb * 64 + 32 + lc];
        const float zo  = Z_s[lb * 64 + 48 + lc];

        const float ig = sigf(xiv + zi);
        const float fg = sigf(xiv + zf + bUf_r);          // reference quirk: uses xi
        const float cn = fg * c_s[tid] + ig * tanhf(xcv + zcv + bUc_r);
        const float og = sigf(xov + zo + bUo_r);
        const float hn = og * tanhf(cn);

        c_s[tid] = cn;
        g_h16[(t + 1) & 1][(gb0 + lb) * 512 + pcol] = __float2half_rn(hn);  // h(t+1)
        __stcs(&out[xidx], hn);                                   // H (streaming)
        __stcs(&out[btd + xidx], cn);                             // C (streaming)

        xiv = xiv_n; xcv = xcv_n; xov = xov_n;
        xidx += DD;

        // Publish flag = t+1 (after all threads' h stores)
        __syncthreads();
        if (tid == 0) {
            __threadfence();
            strelax(myflag, (unsigned)(t + 1));
        }
    }
}

// ----------------------------------------------------------------------------
// Launch
// ----------------------------------------------------------------------------
extern "C" void kernel_launch(void* const* d_in, const int* in_sizes, int n_in,
                              void* d_out, int out_size) {
    (void)in_sizes; (void)n_in; (void)out_size;

    const float* X   = (const float*)d_in[0];
    const float* Wi  = (const float*)d_in[1];
    const float* bi  = (const float*)d_in[2];
    // d_in[3]=Wf, d_in[4]=bf unused (reference computes Xf but never uses it)
    const float* Wc  = (const float*)d_in[5];
    const float* bc  = (const float*)d_in[6];
    const float* Wo  = (const float*)d_in[7];
    const float* bo  = (const float*)d_in[8];
    const float* Ui  = (const float*)d_in[9];
    const float* Uf  = (const float*)d_in[10];
    const float* bUf = (const float*)d_in[11];
    const float* Uc  = (const float*)d_in[12];
    const float* bUc = (const float*)d_in[13];
    const float* Uo  = (const float*)d_in[14];
    const float* bUo = (const float*)d_in[15];
    float* out = (float*)d_out;

    static const int dyn_smem = (64 + 16) * HSTRH * 2;   // 84,480 B
    cudaFuncSetAttribute(lstm_rec_kernel,
                         cudaFuncAttributeMaxDynamicSharedMemorySize, dyn_smem);

    init_kernel<<<128, 256>>>();

    dim3 pgrid(NTOK / 128, 8, 3);
    proj_kernel<<<pgrid, 256>>>(X, Wi, bi, Wc, bc, Wo, bo);

    lstm_rec_kernel<<<NGRP * GBLKS, 256, dyn_smem>>>(Ui, Uf, Uc, Uo, bUf, bUc, bUo, out);
}